// round 11
// baseline (speedup 1.0000x reference)
#include <cuda_runtime.h>
#include <cuda_fp16.h>
#include <cuda_bf16.h>
#include <math.h>

#define NN 50000
#define NE 1600000
#define H 128
#define NG 50
#define NGR 128
#define TABN 8192
#define WMAX 9.6f

// -------- scratch (device globals: allocation-free) --------
__device__ float   g_h[NN * H];
__device__ __half  g_hxh[NN * H];
__device__ float   g_agg[NN * H];
__device__ float   g_w[NE];
__device__ __half2 g_tabhd[TABN * H];     // packed (value, forward-delta)
__device__ float   g_gsum[NGR];
__device__ float   g_gcnt[NGR];
__device__ int     g_cnt[NN];
__device__ int     g_off[NN + 1];
__device__ int     g_cur[NN];
__device__ uint2   g_edges[NE];
__device__ __nv_bfloat16 g_hhi[NN * H],   g_hlo[NN * H];
__device__ __nv_bfloat16 g_agghi[NN * H], g_agglo[NN * H];
__device__ __nv_bfloat16 g_thi[NN * H],   g_tlo[NN * H];
__device__ __nv_bfloat16 g_whi[9 * H * H], g_wlo[9 * H * H];

__device__ __forceinline__ float ssp(float x) {
    return fmaxf(x, 0.0f) + log1pf(expf(-fabsf(x))) - 0.69314718055994531f;
}

__device__ __forceinline__ unsigned sptr(const void* p) {
    return (unsigned)__cvta_generic_to_shared(p);
}

__device__ __forceinline__ void ldsm4(unsigned d[4], unsigned addr) {
    asm volatile("ldmatrix.sync.aligned.m8n8.x4.shared.b16 {%0,%1,%2,%3}, [%4];"
                 : "=r"(d[0]), "=r"(d[1]), "=r"(d[2]), "=r"(d[3]) : "r"(addr));
}

__device__ __forceinline__ void ldsm4t(unsigned d[4], unsigned addr) {
    asm volatile("ldmatrix.sync.aligned.m8n8.x4.trans.shared.b16 {%0,%1,%2,%3}, [%4];"
                 : "=r"(d[0]), "=r"(d[1]), "=r"(d[2]), "=r"(d[3]) : "r"(addr));
}

__device__ __forceinline__ void mma16816(float c[4], const unsigned a[4],
                                         unsigned b0, unsigned b1) {
    asm volatile("mma.sync.aligned.m16n8k16.row.col.f32.bf16.bf16.f32 "
                 "{%0,%1,%2,%3}, {%4,%5,%6,%7}, {%8,%9}, {%0,%1,%2,%3};"
                 : "+f"(c[0]), "+f"(c[1]), "+f"(c[2]), "+f"(c[3])
                 : "r"(a[0]), "r"(a[1]), "r"(a[2]), "r"(a[3]), "r"(b0), "r"(b1));
}

__device__ __forceinline__ unsigned packbf(float x, float y) {
    __nv_bfloat162 t = __floats2bfloat162_rn(x, y);
    return *(unsigned*)&t;
}

__device__ __forceinline__ void bsplit(float x, __nv_bfloat16& hi, __nv_bfloat16& lo) {
    hi = __float2bfloat16(x);
    lo = __float2bfloat16(x - __bfloat162float(hi));
}

// -------- edge geometry + active-edge histogram (fused) --------
__global__ void edge_w_kernel(const float* __restrict__ pos,
                              const float* __restrict__ shift,
                              const int* __restrict__ ei) {
    int e = blockIdx.x * blockDim.x + threadIdx.x;
    if (e >= NE) return;
    int s = ei[e], d = ei[NE + e];
    float dx = pos[s * 3 + 0] - pos[d * 3 + 0] - shift[e * 3 + 0];
    float dy = pos[s * 3 + 1] - pos[d * 3 + 1] - shift[e * 3 + 1];
    float dz = pos[s * 3 + 2] - pos[d * 3 + 2] - shift[e * 3 + 2];
    float w = sqrtf(dx * dx + dy * dy + dz * dz);
    g_w[e] = w;
    if (w < WMAX) atomicAdd(&g_cnt[d], 1);
}

__global__ void embed_kernel(const float* __restrict__ emb, const int* __restrict__ z) {
    int i = blockIdx.x * blockDim.x + threadIdx.x;
    if (i >= NN * H) return;
    int n = i >> 7, c = i & 127;
    float v = emb[z[n] * H + c];
    g_h[i] = v;
    bsplit(v, g_hhi[i], g_hlo[i]);
}

__global__ void zero_misc_kernel() {
    int i = blockIdx.x * blockDim.x + threadIdx.x;
    if (i < NN) g_cnt[i] = 0;
    if (i < NGR) { g_gsum[i] = 0.0f; g_gcnt[i] = 0.0f; }
}

__global__ void wsplit_all_kernel(const float* __restrict__ cf_w1,
                                  const float* __restrict__ cf_w2,
                                  const float* __restrict__ lin_w) {
    int i = blockIdx.x * blockDim.x + threadIdx.x;
    if (i >= 9 * H * H) return;
    int slot = i / (H * H), r = i - slot * (H * H);
    int layer = slot / 3, mat = slot - layer * 3;
    const float* base = (mat == 0) ? cf_w1 : ((mat == 1) ? cf_w2 : lin_w);
    bsplit(base[layer * H * H + r], g_whi[i], g_wlo[i]);
}

__global__ void scan_kernel() {
    __shared__ int warp_sums[32];
    __shared__ int s_carry;
    int tid = threadIdx.x;
    int lane = tid & 31, wid = tid >> 5;
    if (tid == 0) { s_carry = 0; g_off[0] = 0; }
    __syncthreads();
    for (int base = 0; base < NN; base += 1024) {
        int i = base + tid;
        int v = (i < NN) ? g_cnt[i] : 0;
        int x = v;
#pragma unroll
        for (int o = 1; o < 32; o <<= 1) {
            int y = __shfl_up_sync(0xffffffffu, x, o);
            if (lane >= o) x += y;
        }
        if (lane == 31) warp_sums[wid] = x;
        __syncthreads();
        if (wid == 0) {
            int ws = warp_sums[lane];
#pragma unroll
            for (int o = 1; o < 32; o <<= 1) {
                int y = __shfl_up_sync(0xffffffffu, ws, o);
                if (lane >= o) ws += y;
            }
            warp_sums[lane] = ws;
        }
        __syncthreads();
        int incl = x + (wid > 0 ? warp_sums[wid - 1] : 0);
        int total = warp_sums[31];
        int carry = s_carry;
        if (i < NN) {
            g_off[i + 1] = carry + incl;
            g_cur[i] = carry + incl - v;
        }
        __syncthreads();
        if (tid == 0) s_carry = carry + total;
        __syncthreads();
    }
}

__global__ void fill_kernel(const int* __restrict__ ei) {
    int e = blockIdx.x * blockDim.x + threadIdx.x;
    if (e >= NE) return;
    float w = g_w[e];
    if (w >= WMAX) return;
    int d = ei[NE + e];
    int pos = atomicAdd(&g_cur[d], 1);
    float f = w * ((float)(TABN - 1) / WMAX);
    int i0 = (int)f;
    if (i0 > TABN - 2) i0 = TABN - 2;
    float fr = f - (float)i0;
    unsigned short hb = __half_as_ushort(__float2half_rn(fr));
    g_edges[pos] = make_uint2((unsigned)ei[e], ((unsigned)i0 << 16) | hb);
}

// -------- build Wf(w)*C(w) table: 9 samples/block -> 8 (value,delta) pairs --------
__global__ void table_kernel(const float* __restrict__ w1, const float* __restrict__ b1,
                             const float* __restrict__ w2, const float* __restrict__ b2) {
    __shared__ float gs[9][NG];
    __shared__ float t1s[9][H];
    int s0 = blockIdx.x * 8;
    int j = threadIdx.x;
    const float step = WMAX / (float)(TABN - 1);
    const float spacing = 8.0f / 49.0f;
    const float coeff = -0.5f / (spacing * spacing);

    for (int idx = j; idx < 9 * NG; idx += blockDim.x) {
        int m = idx / NG, k = idx - m * NG;
        float ws = (float)(s0 + m) * step;
        float dd = ws - (float)k * spacing;
        gs[m][k] = expf(coeff * dd * dd);
    }
    __syncthreads();

    float acc[9];
#pragma unroll
    for (int m = 0; m < 9; m++) acc[m] = 0.0f;
    for (int k = 0; k < NG; k++) {
        float wv = w1[k * H + j];
#pragma unroll
        for (int m = 0; m < 9; m++) acc[m] += wv * gs[m][k];
    }
    float bb = b1[j];
#pragma unroll
    for (int m = 0; m < 9; m++) t1s[m][j] = ssp(acc[m] + bb);
    __syncthreads();

#pragma unroll
    for (int m = 0; m < 9; m++) acc[m] = 0.0f;
    for (int k = 0; k < H; k++) {
        float wv = w2[k * H + j];
#pragma unroll
        for (int m = 0; m < 9; m++) acc[m] += wv * t1s[m][k];
    }
    float b2v = b2[j];
    float val[9];
#pragma unroll
    for (int m = 0; m < 9; m++) {
        float ws = (float)(s0 + m) * step;
        float C = 0.5f * (cosf(ws * (3.14159265358979f / 8.0f)) + 1.0f);
        val[m] = (acc[m] + b2v) * C;
    }
#pragma unroll
    for (int m = 0; m < 8; m++)
        g_tabhd[(size_t)(s0 + m) * H + j] = __floats2half2_rn(val[m], val[m + 1] - val[m]);
}

// -------- tensor-core node GEMM (round-9 proven version + terms knob) --------
// terms=3: D = Ahi*Whi + Ahi*Wlo + Alo*Whi; terms=2: skip Alo*Whi.
__global__ __launch_bounds__(256) void gemm_mma_kernel(
    const __nv_bfloat16* __restrict__ Ahi, const __nv_bfloat16* __restrict__ Alo,
    const __nv_bfloat16* __restrict__ Whi, const __nv_bfloat16* __restrict__ Wlo,
    const float* __restrict__ bias,
    float* __restrict__ outf,
    __nv_bfloat16* __restrict__ outhi, __nv_bfloat16* __restrict__ outlo,
    __half* __restrict__ outh,
    int act, int residual, int terms) {
    __shared__ __nv_bfloat16 sAhi[128][40];
    __shared__ __nv_bfloat16 sAlo[128][40];
    __shared__ __nv_bfloat16 sWhi[32][136];
    __shared__ __nv_bfloat16 sWlo[32][136];

    int tid = threadIdx.x;
    int wid = tid >> 5, lane = tid & 31;
    int n0 = blockIdx.x * 128;

    float acc[16][4];
#pragma unroll
    for (int t = 0; t < 16; t++)
#pragma unroll
        for (int j = 0; j < 4; j++) acc[t][j] = 0.0f;

    for (int kc = 0; kc < H; kc += 32) {
        __syncthreads();
        for (int i = tid; i < 512; i += 256) {
            int m = i >> 2, c8 = i & 3;
            uint4 vh = make_uint4(0, 0, 0, 0), vl = make_uint4(0, 0, 0, 0);
            if (n0 + m < NN) {
                size_t off = (size_t)(n0 + m) * H + kc + c8 * 8;
                vh = *(const uint4*)(Ahi + off);
                vl = *(const uint4*)(Alo + off);
            }
            *(uint4*)&sAhi[m][c8 * 8] = vh;
            *(uint4*)&sAlo[m][c8 * 8] = vl;
        }
        for (int i = tid; i < 512; i += 256) {
            int r = i >> 4, c8 = i & 15;
            size_t off = (size_t)(kc + r) * H + c8 * 8;
            *(uint4*)&sWhi[r][c8 * 8] = *(const uint4*)(Whi + off);
            *(uint4*)&sWlo[r][c8 * 8] = *(const uint4*)(Wlo + off);
        }
        __syncthreads();

#pragma unroll
        for (int kk = 0; kk < 32; kk += 16) {
            unsigned ahi[4], alo[4];
            unsigned arow = wid * 16 + (lane & 15);
            unsigned acol = kk + (lane >> 4) * 8;
            ldsm4(ahi, sptr(&sAhi[arow][acol]));
            ldsm4(alo, sptr(&sAlo[arow][acol]));
#pragma unroll
            for (int np = 0; np < 8; np++) {
                unsigned bhi[4], blo[4];
                unsigned brow = kk + (lane & 15);
                unsigned bcol = np * 16 + (lane >> 4) * 8;
                ldsm4t(bhi, sptr(&sWhi[brow][bcol]));
                ldsm4t(blo, sptr(&sWlo[brow][bcol]));
                mma16816(acc[2 * np],     ahi, bhi[0], bhi[1]);
                mma16816(acc[2 * np + 1], ahi, bhi[2], bhi[3]);
                mma16816(acc[2 * np],     ahi, blo[0], blo[1]);
                mma16816(acc[2 * np + 1], ahi, blo[2], blo[3]);
                if (terms > 2) {
                    mma16816(acc[2 * np],     alo, bhi[0], bhi[1]);
                    mma16816(acc[2 * np + 1], alo, bhi[2], bhi[3]);
                }
            }
        }
    }

    int r0 = n0 + wid * 16 + (lane >> 2);
    int r1 = r0 + 8;
    int cbase = (lane & 3) * 2;
#pragma unroll
    for (int nt = 0; nt < 16; nt++) {
        int c = nt * 8 + cbase;
        float bx = bias ? bias[c] : 0.0f;
        float by = bias ? bias[c + 1] : 0.0f;
#pragma unroll
        for (int half = 0; half < 2; half++) {
            int r = half ? r1 : r0;
            if (r >= NN) continue;
            float x = acc[nt][2 * half]     + bx;
            float y = acc[nt][2 * half + 1] + by;
            if (act) { x = ssp(x); y = ssp(y); }
            size_t off = (size_t)r * H + c;
            if (outf) {
                float2* op = (float2*)(outf + off);
                if (residual) { float2 o = *op; x += o.x; y += o.y; }
                *op = make_float2(x, y);
            }
            if (outh) {
                __half2 hv = __floats2half2_rn(x, y);
                *(__half2*)(outh + off) = hv;
            }
            if (outhi) {
                unsigned hp = packbf(x, y);
                __nv_bfloat162 hp2 = *(__nv_bfloat162*)&hp;
                float lx = x - __bfloat162float(hp2.x);
                float ly = y - __bfloat162float(hp2.y);
                *(unsigned*)(outhi + off) = hp;
                *(unsigned*)(outlo + off) = packbf(lx, ly);
            }
        }
    }
}

// -------- small GEMM for head (kin=128, kout=64) --------
__global__ void node_gemm_kernel(const float* __restrict__ in, const float* __restrict__ W,
                                 const float* __restrict__ bias, float* __restrict__ out,
                                 int kin, int kout, int act) {
    __shared__ float As[16 * H];
    int n0 = blockIdx.x * 16;
    for (int i = threadIdx.x; i < 16 * kin; i += blockDim.x)
        As[i] = in[n0 * kin + i];
    __syncthreads();
    int j = threadIdx.x;
    if (j < kout) {
        float acc[16];
#pragma unroll
        for (int m = 0; m < 16; m++) acc[m] = 0.0f;
        for (int k = 0; k < kin; k++) {
            float wv = W[k * kout + j];
#pragma unroll
            for (int m = 0; m < 16; m++) acc[m] += wv * As[m * kin + k];
        }
        float b = bias ? bias[j] : 0.0f;
#pragma unroll
        for (int m = 0; m < 16; m++) {
            float v = acc[m] + b;
            if (act) v = ssp(v);
            out[(n0 + m) * kout + j] = v;
        }
    }
}

// -------- gather: one warp per dst node (round-9 proven version) --------
__global__ __launch_bounds__(256) void gather_kernel() {
    int n = (blockIdx.x * blockDim.x + threadIdx.x) >> 5;
    int lane = threadIdx.x & 31;
    if (n >= NN) return;
    int p = g_off[n], end = g_off[n + 1];
    float4 acc = make_float4(0.f, 0.f, 0.f, 0.f);

    for (; p < end; p++) {
        uint2 e0 = g_edges[p];
        int i0 = e0.y >> 16;
        float fr = __half2float(__ushort_as_half((unsigned short)(e0.y & 0xffffu)));
        uint4 td = ((const uint4*)(g_tabhd + (size_t)i0 * H))[lane];
        uint2 hh = ((const uint2*)(g_hxh + (size_t)e0.x * H))[lane];
        float2 vd0 = __half22float2(*(__half2*)&td.x);
        float2 vd1 = __half22float2(*(__half2*)&td.y);
        float2 vd2 = __half22float2(*(__half2*)&td.z);
        float2 vd3 = __half22float2(*(__half2*)&td.w);
        float2 h01 = __half22float2(*(__half2*)&hh.x);
        float2 h23 = __half22float2(*(__half2*)&hh.y);
        acc.x += h01.x * fmaf(fr, vd0.y, vd0.x);
        acc.y += h01.y * fmaf(fr, vd1.y, vd1.x);
        acc.z += h23.x * fmaf(fr, vd2.y, vd2.x);
        acc.w += h23.y * fmaf(fr, vd3.y, vd3.x);
    }
    size_t off = (size_t)n * H + lane * 4;
    unsigned hx0 = packbf(acc.x, acc.y), hx1 = packbf(acc.z, acc.w);
    __nv_bfloat162 h2a = *(__nv_bfloat162*)&hx0;
    __nv_bfloat162 h2b = *(__nv_bfloat162*)&hx1;
    unsigned lx0 = packbf(acc.x - __bfloat162float(h2a.x), acc.y - __bfloat162float(h2a.y));
    unsigned lx1 = packbf(acc.z - __bfloat162float(h2b.x), acc.w - __bfloat162float(h2b.y));
    *(uint2*)(g_agghi + off) = make_uint2(hx0, hx1);
    *(uint2*)(g_agglo + off) = make_uint2(lx0, lx1);
}

// -------- head stage 2 + per-graph reduction --------
__global__ void head2_kernel(const float* __restrict__ w2, const float* __restrict__ b2,
                             const int* __restrict__ batch) {
    int n = (blockIdx.x * blockDim.x + threadIdx.x) >> 5;
    int lane = threadIdx.x & 31;
    if (n >= NN) return;
    float v = g_agg[n * 64 + lane] * w2[lane] + g_agg[n * 64 + 32 + lane] * w2[32 + lane];
#pragma unroll
    for (int o = 16; o > 0; o >>= 1) v += __shfl_down_sync(0xffffffffu, v, o);
    if (lane == 0) {
        int g = batch[n];
        atomicAdd(&g_gsum[g], v + b2[0]);
        atomicAdd(&g_gcnt[g], 1.0f);
    }
}

__global__ void finalize_kernel(float* __restrict__ out) {
    int g = threadIdx.x;
    if (g < NGR) out[g] = g_gsum[g] / fmaxf(g_gcnt[g], 1.0f);
}

extern "C" void kernel_launch(void* const* d_in, const int* in_sizes, int n_in,
                              void* d_out, int out_size) {
    const float* pos     = (const float*)d_in[0];
    const float* shift   = (const float*)d_in[1];
    const float* emb     = (const float*)d_in[2];
    const float* mlp_w1  = (const float*)d_in[3];
    const float* mlp_b1  = (const float*)d_in[4];
    const float* mlp_w2  = (const float*)d_in[5];
    const float* mlp_b2  = (const float*)d_in[6];
    const float* cf_w1   = (const float*)d_in[7];
    const float* cf_w2   = (const float*)d_in[8];
    const float* cf_b2   = (const float*)d_in[9];
    const float* lin_w   = (const float*)d_in[10];
    const float* lin_b   = (const float*)d_in[11];
    const float* head_w1 = (const float*)d_in[12];
    const float* head_b1 = (const float*)d_in[13];
    const float* head_w2 = (const float*)d_in[14];
    const float* head_b2 = (const float*)d_in[15];
    const int*   z       = (const int*)d_in[16];
    const int*   ei      = (const int*)d_in[17];
    const int*   batch   = (const int*)d_in[18];
    float* out = (float*)d_out;

    float *p_h, *p_agg;
    cudaGetSymbolAddress((void**)&p_h,   g_h);
    cudaGetSymbolAddress((void**)&p_agg, g_agg);
    __half* p_hxh;
    cudaGetSymbolAddress((void**)&p_hxh, g_hxh);
    __nv_bfloat16 *p_hhi, *p_hlo, *p_agghi, *p_agglo, *p_thi, *p_tlo, *p_whi, *p_wlo;
    cudaGetSymbolAddress((void**)&p_hhi,   g_hhi);
    cudaGetSymbolAddress((void**)&p_hlo,   g_hlo);
    cudaGetSymbolAddress((void**)&p_agghi, g_agghi);
    cudaGetSymbolAddress((void**)&p_agglo, g_agglo);
    cudaGetSymbolAddress((void**)&p_thi,   g_thi);
    cudaGetSymbolAddress((void**)&p_tlo,   g_tlo);
    cudaGetSymbolAddress((void**)&p_whi,   g_whi);
    cudaGetSymbolAddress((void**)&p_wlo,   g_wlo);

    const int mma_blocks = (NN + 127) / 128;
    const int HH = H * H;

    // Launch order chosen so launch #4 (the profiled one) is gemm_mma.
    zero_misc_kernel<<<(NN + 255) / 256, 256>>>();                       // 1
    embed_kernel<<<(NN * H + 255) / 256, 256>>>(emb, z);                 // 2
    wsplit_all_kernel<<<(9 * HH + 255) / 256, 256>>>(cf_w1, cf_w2, lin_w); // 3
    // 4: hx(i=0) = h @ cf_w1[0]  -> fp16  (2-term split: hx is fp16 anyway)
    gemm_mma_kernel<<<mma_blocks, 256>>>(p_hhi, p_hlo, p_whi, p_wlo,
                                         nullptr, nullptr, nullptr, nullptr,
                                         p_hxh, 0, 0, 2);
    edge_w_kernel<<<(NE + 255) / 256, 256>>>(pos, shift, ei);            // 5
    scan_kernel<<<1, 1024>>>();                                          // 6
    fill_kernel<<<(NE + 255) / 256, 256>>>(ei);                          // 7

    for (int i = 0; i < 3; i++) {
        table_kernel<<<TABN / 8, 128>>>(mlp_w1 + i * NG * H, mlp_b1 + i * H,
                                        mlp_w2 + i * HH,  mlp_b2 + i * H);
        if (i > 0) {
            gemm_mma_kernel<<<mma_blocks, 256>>>(p_hhi, p_hlo,
                                                 p_whi + (i * 3 + 0) * HH, p_wlo + (i * 3 + 0) * HH,
                                                 nullptr, nullptr, nullptr, nullptr,
                                                 p_hxh, 0, 0, 2);
        }
        gather_kernel<<<(NN * 32 + 255) / 256, 256>>>();
        gemm_mma_kernel<<<mma_blocks, 256>>>(p_agghi, p_agglo,
                                             p_whi + (i * 3 + 1) * HH, p_wlo + (i * 3 + 1) * HH,
                                             cf_b2 + i * H, nullptr, p_thi, p_tlo, nullptr, 1, 0, 3);
        gemm_mma_kernel<<<mma_blocks, 256>>>(p_thi, p_tlo,
                                             p_whi + (i * 3 + 2) * HH, p_wlo + (i * 3 + 2) * HH,
                                             lin_b + i * H, p_h, p_hhi, p_hlo, nullptr, 0, 1, 3);
    }

    node_gemm_kernel<<<(NN + 15) / 16, 128>>>(p_h, head_w1, head_b1, p_agg, H, 64, 1);
    head2_kernel<<<(NN * 32 + 255) / 256, 256>>>(head_w2, head_b2, batch);
    finalize_kernel<<<1, 128>>>(out);
}

// round 12
// speedup vs baseline: 1.1544x; 1.1544x over previous
#include <cuda_runtime.h>
#include <cuda_fp16.h>
#include <cuda_bf16.h>
#include <math.h>

#define NN 50000
#define NE 1600000
#define H 128
#define NG 50
#define NGR 128
#define TABN 8192
#define WMAX 9.6f

// -------- scratch (device globals: allocation-free) --------
__device__ float   g_h[NN * H];
__device__ __half  g_hxh[NN * H];
__device__ float   g_agg[NN * H];
__device__ float   g_w[NE];
__device__ __half2 g_tabhd[TABN * H];     // packed (value, forward-delta)
__device__ float   g_gsum[NGR];
__device__ float   g_gcnt[NGR];
__device__ int     g_cnt[NN];
__device__ int     g_off[NN + 1];
__device__ int     g_cur[NN];
__device__ uint2   g_edges[NE];
__device__ __nv_bfloat16 g_hhi[NN * H],   g_hlo[NN * H];
__device__ __nv_bfloat16 g_agghi[NN * H], g_agglo[NN * H];
__device__ __nv_bfloat16 g_thi[NN * H],   g_tlo[NN * H];
__device__ __nv_bfloat16 g_whi[9 * H * H], g_wlo[9 * H * H];

__device__ __forceinline__ float ssp(float x) {
    return fmaxf(x, 0.0f) + log1pf(expf(-fabsf(x))) - 0.69314718055994531f;
}

__device__ __forceinline__ unsigned sptr(const void* p) {
    return (unsigned)__cvta_generic_to_shared(p);
}

__device__ __forceinline__ void ldsm4(unsigned d[4], unsigned addr) {
    asm volatile("ldmatrix.sync.aligned.m8n8.x4.shared.b16 {%0,%1,%2,%3}, [%4];"
                 : "=r"(d[0]), "=r"(d[1]), "=r"(d[2]), "=r"(d[3]) : "r"(addr));
}

__device__ __forceinline__ void ldsm4t(unsigned d[4], unsigned addr) {
    asm volatile("ldmatrix.sync.aligned.m8n8.x4.trans.shared.b16 {%0,%1,%2,%3}, [%4];"
                 : "=r"(d[0]), "=r"(d[1]), "=r"(d[2]), "=r"(d[3]) : "r"(addr));
}

__device__ __forceinline__ void mma16816(float c[4], const unsigned a[4],
                                         unsigned b0, unsigned b1) {
    asm volatile("mma.sync.aligned.m16n8k16.row.col.f32.bf16.bf16.f32 "
                 "{%0,%1,%2,%3}, {%4,%5,%6,%7}, {%8,%9}, {%0,%1,%2,%3};"
                 : "+f"(c[0]), "+f"(c[1]), "+f"(c[2]), "+f"(c[3])
                 : "r"(a[0]), "r"(a[1]), "r"(a[2]), "r"(a[3]), "r"(b0), "r"(b1));
}

__device__ __forceinline__ unsigned packbf(float x, float y) {
    __nv_bfloat162 t = __floats2bfloat162_rn(x, y);
    return *(unsigned*)&t;
}

__device__ __forceinline__ void bsplit(float x, __nv_bfloat16& hi, __nv_bfloat16& lo) {
    hi = __float2bfloat16(x);
    lo = __float2bfloat16(x - __bfloat162float(hi));
}

// -------- edge geometry + active-edge histogram (fused) --------
__global__ void edge_w_kernel(const float* __restrict__ pos,
                              const float* __restrict__ shift,
                              const int* __restrict__ ei) {
    int e = blockIdx.x * blockDim.x + threadIdx.x;
    if (e >= NE) return;
    int s = ei[e], d = ei[NE + e];
    float dx = pos[s * 3 + 0] - pos[d * 3 + 0] - shift[e * 3 + 0];
    float dy = pos[s * 3 + 1] - pos[d * 3 + 1] - shift[e * 3 + 1];
    float dz = pos[s * 3 + 2] - pos[d * 3 + 2] - shift[e * 3 + 2];
    float w = sqrtf(dx * dx + dy * dy + dz * dz);
    g_w[e] = w;
    if (w < WMAX) atomicAdd(&g_cnt[d], 1);
}

__global__ void embed_kernel(const float* __restrict__ emb, const int* __restrict__ z) {
    int i = blockIdx.x * blockDim.x + threadIdx.x;
    if (i >= NN * H) return;
    int n = i >> 7, c = i & 127;
    float v = emb[z[n] * H + c];
    g_h[i] = v;
    bsplit(v, g_hhi[i], g_hlo[i]);
}

__global__ void zero_misc_kernel() {
    int i = blockIdx.x * blockDim.x + threadIdx.x;
    if (i < NN) g_cnt[i] = 0;
    if (i < NGR) { g_gsum[i] = 0.0f; g_gcnt[i] = 0.0f; }
}

__global__ void wsplit_all_kernel(const float* __restrict__ cf_w1,
                                  const float* __restrict__ cf_w2,
                                  const float* __restrict__ lin_w) {
    int i = blockIdx.x * blockDim.x + threadIdx.x;
    if (i >= 9 * H * H) return;
    int slot = i / (H * H), r = i - slot * (H * H);
    int layer = slot / 3, mat = slot - layer * 3;
    const float* base = (mat == 0) ? cf_w1 : ((mat == 1) ? cf_w2 : lin_w);
    bsplit(base[layer * H * H + r], g_whi[i], g_wlo[i]);
}

__global__ void scan_kernel() {
    __shared__ int warp_sums[32];
    __shared__ int s_carry;
    int tid = threadIdx.x;
    int lane = tid & 31, wid = tid >> 5;
    if (tid == 0) { s_carry = 0; g_off[0] = 0; }
    __syncthreads();
    for (int base = 0; base < NN; base += 1024) {
        int i = base + tid;
        int v = (i < NN) ? g_cnt[i] : 0;
        int x = v;
#pragma unroll
        for (int o = 1; o < 32; o <<= 1) {
            int y = __shfl_up_sync(0xffffffffu, x, o);
            if (lane >= o) x += y;
        }
        if (lane == 31) warp_sums[wid] = x;
        __syncthreads();
        if (wid == 0) {
            int ws = warp_sums[lane];
#pragma unroll
            for (int o = 1; o < 32; o <<= 1) {
                int y = __shfl_up_sync(0xffffffffu, ws, o);
                if (lane >= o) ws += y;
            }
            warp_sums[lane] = ws;
        }
        __syncthreads();
        int incl = x + (wid > 0 ? warp_sums[wid - 1] : 0);
        int total = warp_sums[31];
        int carry = s_carry;
        if (i < NN) {
            g_off[i + 1] = carry + incl;
            g_cur[i] = carry + incl - v;
        }
        __syncthreads();
        if (tid == 0) s_carry = carry + total;
        __syncthreads();
    }
}

__global__ void fill_kernel(const int* __restrict__ ei) {
    int e = blockIdx.x * blockDim.x + threadIdx.x;
    if (e >= NE) return;
    float w = g_w[e];
    if (w >= WMAX) return;
    int d = ei[NE + e];
    int pos = atomicAdd(&g_cur[d], 1);
    float f = w * ((float)(TABN - 1) / WMAX);
    int i0 = (int)f;
    if (i0 > TABN - 2) i0 = TABN - 2;
    float fr = f - (float)i0;
    unsigned short hb = __half_as_ushort(__float2half_rn(fr));
    g_edges[pos] = make_uint2((unsigned)ei[e], ((unsigned)i0 << 16) | hb);
}

// -------- build Wf(w)*C(w) table: 9 samples/block -> 8 (value,delta) pairs --------
__global__ void table_kernel(const float* __restrict__ w1, const float* __restrict__ b1,
                             const float* __restrict__ w2, const float* __restrict__ b2) {
    __shared__ float gs[9][NG];
    __shared__ float t1s[9][H];
    int s0 = blockIdx.x * 8;
    int j = threadIdx.x;
    const float step = WMAX / (float)(TABN - 1);
    const float spacing = 8.0f / 49.0f;
    const float coeff = -0.5f / (spacing * spacing);

    for (int idx = j; idx < 9 * NG; idx += blockDim.x) {
        int m = idx / NG, k = idx - m * NG;
        float ws = (float)(s0 + m) * step;
        float dd = ws - (float)k * spacing;
        gs[m][k] = expf(coeff * dd * dd);
    }
    __syncthreads();

    float acc[9];
#pragma unroll
    for (int m = 0; m < 9; m++) acc[m] = 0.0f;
    for (int k = 0; k < NG; k++) {
        float wv = w1[k * H + j];
#pragma unroll
        for (int m = 0; m < 9; m++) acc[m] += wv * gs[m][k];
    }
    float bb = b1[j];
#pragma unroll
    for (int m = 0; m < 9; m++) t1s[m][j] = ssp(acc[m] + bb);
    __syncthreads();

#pragma unroll
    for (int m = 0; m < 9; m++) acc[m] = 0.0f;
    for (int k = 0; k < H; k++) {
        float wv = w2[k * H + j];
#pragma unroll
        for (int m = 0; m < 9; m++) acc[m] += wv * t1s[m][k];
    }
    float b2v = b2[j];
    float val[9];
#pragma unroll
    for (int m = 0; m < 9; m++) {
        float ws = (float)(s0 + m) * step;
        float C = 0.5f * (cosf(ws * (3.14159265358979f / 8.0f)) + 1.0f);
        val[m] = (acc[m] + b2v) * C;
    }
#pragma unroll
    for (int m = 0; m < 8; m++)
        g_tabhd[(size_t)(s0 + m) * H + j] = __floats2half2_rn(val[m], val[m + 1] - val[m]);
}

// -------- tensor-core node GEMM: 64x128 tile, 8 warps (4M x 2N), 3-term split ----
// D = Ahi*Whi + Ahi*Wlo + Alo*Whi (fp32 accum). acc = 32 regs/thread.
__global__ __launch_bounds__(256, 3) void gemm_mma_kernel(
    const __nv_bfloat16* __restrict__ Ahi, const __nv_bfloat16* __restrict__ Alo,
    const __nv_bfloat16* __restrict__ Whi, const __nv_bfloat16* __restrict__ Wlo,
    const float* __restrict__ bias,
    float* __restrict__ outf,
    __nv_bfloat16* __restrict__ outhi, __nv_bfloat16* __restrict__ outlo,
    __half* __restrict__ outh,
    int act, int residual) {
    __shared__ __nv_bfloat16 sAhi[64][40];    // 5.1 KB
    __shared__ __nv_bfloat16 sAlo[64][40];    // 5.1 KB
    __shared__ __nv_bfloat16 sWhi[32][136];   // 8.7 KB
    __shared__ __nv_bfloat16 sWlo[32][136];   // 8.7 KB

    int tid = threadIdx.x;
    int wid = tid >> 5, lane = tid & 31;
    int mwarp = wid & 3;         // m-strip 0..3 (16 rows each)
    int nwarp = wid >> 2;        // n-half 0..1 (64 cols each)
    int n0 = blockIdx.x * 64;

    float acc[8][4];             // 8 n-tiles x 4
#pragma unroll
    for (int t = 0; t < 8; t++)
#pragma unroll
        for (int j = 0; j < 4; j++) acc[t][j] = 0.0f;

    for (int kc = 0; kc < H; kc += 32) {
        __syncthreads();
        // stage A chunk: 64 rows x 32 bf16 = 256 uint4 per buffer -> 1 per thread
        {
            int m = tid >> 2, c8 = tid & 3;
            uint4 vh = make_uint4(0, 0, 0, 0), vl = make_uint4(0, 0, 0, 0);
            if (n0 + m < NN) {
                size_t off = (size_t)(n0 + m) * H + kc + c8 * 8;
                vh = *(const uint4*)(Ahi + off);
                vl = *(const uint4*)(Alo + off);
            }
            *(uint4*)&sAhi[m][c8 * 8] = vh;
            *(uint4*)&sAlo[m][c8 * 8] = vl;
        }
        // stage W chunk: 32 rows x 128 bf16 = 512 uint4 per buffer -> 2 per thread
        for (int i = tid; i < 512; i += 256) {
            int r = i >> 4, c8 = i & 15;
            size_t off = (size_t)(kc + r) * H + c8 * 8;
            *(uint4*)&sWhi[r][c8 * 8] = *(const uint4*)(Whi + off);
            *(uint4*)&sWlo[r][c8 * 8] = *(const uint4*)(Wlo + off);
        }
        __syncthreads();

#pragma unroll
        for (int kk = 0; kk < 32; kk += 16) {
            unsigned ahi[4], alo[4];
            unsigned arow = mwarp * 16 + (lane & 15);
            unsigned acol = kk + (lane >> 4) * 8;
            ldsm4(ahi, sptr(&sAhi[arow][acol]));
            ldsm4(alo, sptr(&sAlo[arow][acol]));
#pragma unroll
            for (int j = 0; j < 4; j++) {            // 4 x 16-col groups
                unsigned bhi[4], blo[4];
                unsigned brow = kk + (lane & 15);
                unsigned bcol = nwarp * 64 + j * 16 + (lane >> 4) * 8;
                ldsm4t(bhi, sptr(&sWhi[brow][bcol]));
                ldsm4t(blo, sptr(&sWlo[brow][bcol]));
                mma16816(acc[2 * j],     ahi, bhi[0], bhi[1]);
                mma16816(acc[2 * j + 1], ahi, bhi[2], bhi[3]);
                mma16816(acc[2 * j],     ahi, blo[0], blo[1]);
                mma16816(acc[2 * j + 1], ahi, blo[2], blo[3]);
                mma16816(acc[2 * j],     alo, bhi[0], bhi[1]);
                mma16816(acc[2 * j + 1], alo, bhi[2], bhi[3]);
            }
        }
    }

    int r0 = n0 + mwarp * 16 + (lane >> 2);
    int r1 = r0 + 8;
    int cbase = nwarp * 64 + (lane & 3) * 2;
#pragma unroll
    for (int nt = 0; nt < 8; nt++) {
        int c = cbase + nt * 8;
        float bx = bias ? bias[c] : 0.0f;
        float by = bias ? bias[c + 1] : 0.0f;
#pragma unroll
        for (int half = 0; half < 2; half++) {
            int r = half ? r1 : r0;
            if (r >= NN) continue;
            float x = acc[nt][2 * half]     + bx;
            float y = acc[nt][2 * half + 1] + by;
            if (act) { x = ssp(x); y = ssp(y); }
            size_t off = (size_t)r * H + c;
            if (outf) {
                float2* op = (float2*)(outf + off);
                if (residual) { float2 o = *op; x += o.x; y += o.y; }
                *op = make_float2(x, y);
            }
            if (outh) {
                __half2 hv = __floats2half2_rn(x, y);
                *(__half2*)(outh + off) = hv;
            }
            if (outhi) {
                unsigned hp = packbf(x, y);
                __nv_bfloat162 hp2 = *(__nv_bfloat162*)&hp;
                float lx = x - __bfloat162float(hp2.x);
                float ly = y - __bfloat162float(hp2.y);
                *(unsigned*)(outhi + off) = hp;
                *(unsigned*)(outlo + off) = packbf(lx, ly);
            }
        }
    }
}

// -------- small GEMM for head (kin=128, kout=64) --------
__global__ void node_gemm_kernel(const float* __restrict__ in, const float* __restrict__ W,
                                 const float* __restrict__ bias, float* __restrict__ out,
                                 int kin, int kout, int act) {
    __shared__ float As[16 * H];
    int n0 = blockIdx.x * 16;
    for (int i = threadIdx.x; i < 16 * kin; i += blockDim.x)
        As[i] = in[n0 * kin + i];
    __syncthreads();
    int j = threadIdx.x;
    if (j < kout) {
        float acc[16];
#pragma unroll
        for (int m = 0; m < 16; m++) acc[m] = 0.0f;
        for (int k = 0; k < kin; k++) {
            float wv = W[k * kout + j];
#pragma unroll
            for (int m = 0; m < 16; m++) acc[m] += wv * As[m * kin + k];
        }
        float b = bias ? bias[j] : 0.0f;
#pragma unroll
        for (int m = 0; m < 16; m++) {
            float v = acc[m] + b;
            if (act) v = ssp(v);
            out[(n0 + m) * kout + j] = v;
        }
    }
}

// -------- gather: one warp per dst node (round-9 proven version) --------
__global__ __launch_bounds__(256) void gather_kernel() {
    int n = (blockIdx.x * blockDim.x + threadIdx.x) >> 5;
    int lane = threadIdx.x & 31;
    if (n >= NN) return;
    int p = g_off[n], end = g_off[n + 1];
    float4 acc = make_float4(0.f, 0.f, 0.f, 0.f);

    for (; p < end; p++) {
        uint2 e0 = g_edges[p];
        int i0 = e0.y >> 16;
        float fr = __half2float(__ushort_as_half((unsigned short)(e0.y & 0xffffu)));
        uint4 td = ((const uint4*)(g_tabhd + (size_t)i0 * H))[lane];
        uint2 hh = ((const uint2*)(g_hxh + (size_t)e0.x * H))[lane];
        float2 vd0 = __half22float2(*(__half2*)&td.x);
        float2 vd1 = __half22float2(*(__half2*)&td.y);
        float2 vd2 = __half22float2(*(__half2*)&td.z);
        float2 vd3 = __half22float2(*(__half2*)&td.w);
        float2 h01 = __half22float2(*(__half2*)&hh.x);
        float2 h23 = __half22float2(*(__half2*)&hh.y);
        acc.x += h01.x * fmaf(fr, vd0.y, vd0.x);
        acc.y += h01.y * fmaf(fr, vd1.y, vd1.x);
        acc.z += h23.x * fmaf(fr, vd2.y, vd2.x);
        acc.w += h23.y * fmaf(fr, vd3.y, vd3.x);
    }
    size_t off = (size_t)n * H + lane * 4;
    unsigned hx0 = packbf(acc.x, acc.y), hx1 = packbf(acc.z, acc.w);
    __nv_bfloat162 h2a = *(__nv_bfloat162*)&hx0;
    __nv_bfloat162 h2b = *(__nv_bfloat162*)&hx1;
    unsigned lx0 = packbf(acc.x - __bfloat162float(h2a.x), acc.y - __bfloat162float(h2a.y));
    unsigned lx1 = packbf(acc.z - __bfloat162float(h2b.x), acc.w - __bfloat162float(h2b.y));
    *(uint2*)(g_agghi + off) = make_uint2(hx0, hx1);
    *(uint2*)(g_agglo + off) = make_uint2(lx0, lx1);
}

// -------- head stage 2 + per-graph reduction --------
__global__ void head2_kernel(const float* __restrict__ w2, const float* __restrict__ b2,
                             const int* __restrict__ batch) {
    int n = (blockIdx.x * blockDim.x + threadIdx.x) >> 5;
    int lane = threadIdx.x & 31;
    if (n >= NN) return;
    float v = g_agg[n * 64 + lane] * w2[lane] + g_agg[n * 64 + 32 + lane] * w2[32 + lane];
#pragma unroll
    for (int o = 16; o > 0; o >>= 1) v += __shfl_down_sync(0xffffffffu, v, o);
    if (lane == 0) {
        int g = batch[n];
        atomicAdd(&g_gsum[g], v + b2[0]);
        atomicAdd(&g_gcnt[g], 1.0f);
    }
}

__global__ void finalize_kernel(float* __restrict__ out) {
    int g = threadIdx.x;
    if (g < NGR) out[g] = g_gsum[g] / fmaxf(g_gcnt[g], 1.0f);
}

extern "C" void kernel_launch(void* const* d_in, const int* in_sizes, int n_in,
                              void* d_out, int out_size) {
    const float* pos     = (const float*)d_in[0];
    const float* shift   = (const float*)d_in[1];
    const float* emb     = (const float*)d_in[2];
    const float* mlp_w1  = (const float*)d_in[3];
    const float* mlp_b1  = (const float*)d_in[4];
    const float* mlp_w2  = (const float*)d_in[5];
    const float* mlp_b2  = (const float*)d_in[6];
    const float* cf_w1   = (const float*)d_in[7];
    const float* cf_w2   = (const float*)d_in[8];
    const float* cf_b2   = (const float*)d_in[9];
    const float* lin_w   = (const float*)d_in[10];
    const float* lin_b   = (const float*)d_in[11];
    const float* head_w1 = (const float*)d_in[12];
    const float* head_b1 = (const float*)d_in[13];
    const float* head_w2 = (const float*)d_in[14];
    const float* head_b2 = (const float*)d_in[15];
    const int*   z       = (const int*)d_in[16];
    const int*   ei      = (const int*)d_in[17];
    const int*   batch   = (const int*)d_in[18];
    float* out = (float*)d_out;

    float *p_h, *p_agg;
    cudaGetSymbolAddress((void**)&p_h,   g_h);
    cudaGetSymbolAddress((void**)&p_agg, g_agg);
    __half* p_hxh;
    cudaGetSymbolAddress((void**)&p_hxh, g_hxh);
    __nv_bfloat16 *p_hhi, *p_hlo, *p_agghi, *p_agglo, *p_thi, *p_tlo, *p_whi, *p_wlo;
    cudaGetSymbolAddress((void**)&p_hhi,   g_hhi);
    cudaGetSymbolAddress((void**)&p_hlo,   g_hlo);
    cudaGetSymbolAddress((void**)&p_agghi, g_agghi);
    cudaGetSymbolAddress((void**)&p_agglo, g_agglo);
    cudaGetSymbolAddress((void**)&p_thi,   g_thi);
    cudaGetSymbolAddress((void**)&p_tlo,   g_tlo);
    cudaGetSymbolAddress((void**)&p_whi,   g_whi);
    cudaGetSymbolAddress((void**)&p_wlo,   g_wlo);

    const int mma_blocks = (NN + 63) / 64;
    const int HH = H * H;

    // Launch order chosen so launch #4 (the profiled one) is gemm_mma.
    zero_misc_kernel<<<(NN + 255) / 256, 256>>>();                         // 1
    embed_kernel<<<(NN * H + 255) / 256, 256>>>(emb, z);                   // 2
    wsplit_all_kernel<<<(9 * HH + 255) / 256, 256>>>(cf_w1, cf_w2, lin_w); // 3
    // 4: hx(i=0) = h @ cf_w1[0] -> fp16
    gemm_mma_kernel<<<mma_blocks, 256>>>(p_hhi, p_hlo, p_whi, p_wlo,
                                         nullptr, nullptr, nullptr, nullptr,
                                         p_hxh, 0, 0);
    edge_w_kernel<<<(NE + 255) / 256, 256>>>(pos, shift, ei);              // 5
    scan_kernel<<<1, 1024>>>();                                            // 6
    fill_kernel<<<(NE + 255) / 256, 256>>>(ei);                            // 7

    for (int i = 0; i < 3; i++) {
        table_kernel<<<TABN / 8, 128>>>(mlp_w1 + i * NG * H, mlp_b1 + i * H,
                                        mlp_w2 + i * HH,  mlp_b2 + i * H);
        if (i > 0) {
            gemm_mma_kernel<<<mma_blocks, 256>>>(p_hhi, p_hlo,
                                                 p_whi + (i * 3 + 0) * HH, p_wlo + (i * 3 + 0) * HH,
                                                 nullptr, nullptr, nullptr, nullptr,
                                                 p_hxh, 0, 0);
        }
        gather_kernel<<<(NN * 32 + 255) / 256, 256>>>();
        gemm_mma_kernel<<<mma_blocks, 256>>>(p_agghi, p_agglo,
                                             p_whi + (i * 3 + 1) * HH, p_wlo + (i * 3 + 1) * HH,
                                             cf_b2 + i * H, nullptr, p_thi, p_tlo, nullptr, 1, 0);
        gemm_mma_kernel<<<mma_blocks, 256>>>(p_thi, p_tlo,
                                             p_whi + (i * 3 + 2) * HH, p_wlo + (i * 3 + 2) * HH,
                                             lin_b + i * H, p_h, p_hhi, p_hlo, nullptr, 0, 1);
    }

    node_gemm_kernel<<<(NN + 15) / 16, 128>>>(p_h, head_w1, head_b1, p_agg, H, 64, 1);
    head2_kernel<<<(NN * 32 + 255) / 256, 256>>>(head_w2, head_b2, batch);
    finalize_kernel<<<1, 128>>>(out);
}